// round 2
// baseline (speedup 1.0000x reference)
#include <cuda_runtime.h>
#include <cuda_bf16.h>

#define MAX_NODES 50000
#define F 128

// Scratch (device globals; allocation-free per harness rules)
__device__ float g_agg[MAX_NODES * F];
__device__ float g_h[MAX_NODES * F];
__device__ float g_stats[2 * F];       // [0:128) sum, [128:256) sumsq
__device__ float g_W2p[F * F];
__device__ float g_b2p[F];
__device__ int   g_src[800000];
__device__ int   g_dst[800000];
__device__ int   g_is64;

// ---------------------------------------------------------------------------
// K-1: detect whether edge_index is int64 (all odd 32-bit words zero) or int32
// ---------------------------------------------------------------------------
__global__ void detect_kernel(const int* __restrict__ ei, int n_words) {
    // sample up to 2048 odd words spread across the buffer
    int nz = 0;
    for (int i = threadIdx.x; i < 2048; i += 32) {
        int w = 2 * i + 1;
        if (w < n_words && ei[w] != 0) nz = 1;
    }
    nz = __any_sync(0xffffffffu, nz);
    if (threadIdx.x == 0) g_is64 = nz ? 0 : 1;
}

// ---------------------------------------------------------------------------
// K-0b: unpack edge indices into int32 g_src/g_dst with bounds guard
// ---------------------------------------------------------------------------
__global__ void convert_kernel(const void* __restrict__ eiv, int n_edges,
                               int n_nodes) {
    int e = blockIdx.x * blockDim.x + threadIdx.x;
    if (e >= n_edges) return;
    long long s, d;
    if (g_is64) {
        const long long* ei = (const long long*)eiv;
        s = ei[e];
        d = ei[n_edges + e];
    } else {
        const int* ei = (const int*)eiv;
        s = ei[e];
        d = ei[n_edges + e];
    }
    g_src[e] = (s >= 0 && s < n_nodes) ? (int)s : -1;
    g_dst[e] = (d >= 0 && d < n_nodes) ? (int)d : -1;
}

// ---------------------------------------------------------------------------
// K0: agg = x (self term), zero stats
// ---------------------------------------------------------------------------
__global__ void init_kernel(const float* __restrict__ x, int n4) {
    int i = blockIdx.x * blockDim.x + threadIdx.x;
    if (i < 2 * F) g_stats[i] = 0.0f;
    if (i < n4) ((float4*)g_agg)[i] = ((const float4*)x)[i];
}

// ---------------------------------------------------------------------------
// K1: scatter-add: agg[dst] += x[src], one warp per edge, vector REDs
// ---------------------------------------------------------------------------
__global__ void scatter_kernel(const float* __restrict__ x, int n_edges) {
    int gt = blockIdx.x * blockDim.x + threadIdx.x;
    int e = gt >> 5;
    int lane = gt & 31;
    if (e >= n_edges) return;
    int s = g_src[e];
    int d = g_dst[e];
    if (s < 0 || d < 0) return;
    float4 v = ((const float4*)(x + (size_t)s * F))[lane];
    float* dst = g_agg + (size_t)d * F + lane * 4;
    asm volatile("red.global.add.v4.f32 [%0], {%1,%2,%3,%4};"
                 :: "l"(dst), "f"(v.x), "f"(v.y), "f"(v.z), "f"(v.w)
                 : "memory");
}

// ---------------------------------------------------------------------------
// GEMM: out[m][n] = act( sum_k A[m][k] * W[n][k] + bias[n] )
// Tile: 64 rows x 128 cols per block, K=128 resident in smem.
// Threads 256 as (ty=tid/32 -> 8 rows each, tx=tid%32 -> cols n = tx + 32*j).
// smem pitch 132 floats => LDS.128 conflict-free; A reads are warp-uniform.
// FIRST pass: A=g_agg, W/bias from args, out=g_h, ReLU + BN-stat accumulation.
// Second pass: A=g_h, W=g_W2p, bias=g_b2p, out=arg (d_out), no activation.
// ---------------------------------------------------------------------------
#define PITCH 132
#define GEMM_SMEM ((64 + 128) * PITCH * 4)

template <bool FIRST>
__global__ void __launch_bounds__(256, 2)
gemm_kernel(const float* __restrict__ Wp, const float* __restrict__ biasp,
            float* __restrict__ outp, int M) {
    extern __shared__ float smem[];
    float* As = smem;               // 64 x PITCH
    float* Ws = smem + 64 * PITCH;  // 128 x PITCH

    const float* A    = FIRST ? g_agg : g_h;
    const float* W    = FIRST ? Wp    : g_W2p;
    const float* bias = FIRST ? biasp : g_b2p;
    float* out        = FIRST ? g_h   : outp;

    int tid = threadIdx.x;
    int m0 = blockIdx.x * 64;

    // Load W (128x128), coalesced float4, store pitch-132
#pragma unroll
    for (int p = 0; p < 16; p++) {
        int idx = tid + p * 256;            // float4 index
        int r = idx >> 5, c4 = idx & 31;
        float4 v = ((const float4*)W)[idx];
        *(float4*)&Ws[r * PITCH + c4 * 4] = v;
    }
    // Load A tile (64x128) with row guard
#pragma unroll
    for (int p = 0; p < 8; p++) {
        int idx = tid + p * 256;
        int r = idx >> 5, c4 = idx & 31;
        int m = m0 + r;
        float4 v = make_float4(0.f, 0.f, 0.f, 0.f);
        if (m < M) v = ((const float4*)A)[(size_t)m * 32 + c4];
        *(float4*)&As[r * PITCH + c4 * 4] = v;
    }
    __syncthreads();

    int tx = tid & 31, ty = tid >> 5;
    float acc[8][4];
#pragma unroll
    for (int i = 0; i < 8; i++)
#pragma unroll
        for (int j = 0; j < 4; j++) acc[i][j] = 0.0f;

#pragma unroll 4
    for (int k4 = 0; k4 < 32; k4++) {
        float4 wv[4];
#pragma unroll
        for (int j = 0; j < 4; j++)
            wv[j] = *(const float4*)&Ws[(tx + 32 * j) * PITCH + k4 * 4];
#pragma unroll
        for (int i = 0; i < 8; i++) {
            float4 av = *(const float4*)&As[(ty * 8 + i) * PITCH + k4 * 4];
#pragma unroll
            for (int j = 0; j < 4; j++) {
                acc[i][j] += av.x * wv[j].x;
                acc[i][j] += av.y * wv[j].y;
                acc[i][j] += av.z * wv[j].z;
                acc[i][j] += av.w * wv[j].w;
            }
        }
    }
    __syncthreads();  // smem reused below for stats reduction

    float b[4];
#pragma unroll
    for (int j = 0; j < 4; j++) b[j] = bias[tx + 32 * j];

    float colS[4] = {0.f, 0.f, 0.f, 0.f};
    float colQ[4] = {0.f, 0.f, 0.f, 0.f};
#pragma unroll
    for (int i = 0; i < 8; i++) {
        int m = m0 + ty * 8 + i;
        if (m < M) {
#pragma unroll
            for (int j = 0; j < 4; j++) {
                float v = acc[i][j] + b[j];
                if (FIRST) v = fmaxf(v, 0.0f);
                out[(size_t)m * F + tx + 32 * j] = v;
                if (FIRST) { colS[j] += v; colQ[j] += v * v; }
            }
        }
    }

    if (FIRST) {
        float* redS = smem;          // 8 x 128
        float* redQ = smem + 1024;   // 8 x 128
#pragma unroll
        for (int j = 0; j < 4; j++) {
            redS[ty * F + tx + 32 * j] = colS[j];
            redQ[ty * F + tx + 32 * j] = colQ[j];
        }
        __syncthreads();
        if (tid < F) {
            float s = 0.f;
#pragma unroll
            for (int t = 0; t < 8; t++) s += redS[t * F + tid];
            atomicAdd(&g_stats[tid], s);
        } else {
            int c = tid - F;
            float q = 0.f;
#pragma unroll
            for (int t = 0; t < 8; t++) q += redQ[t * F + c];
            atomicAdd(&g_stats[F + c], q);
        }
    }
}

// ---------------------------------------------------------------------------
// K3: fold BN into W2/b2:  s = gamma*rsqrt(var+eps), t = beta - mean*s
//     W2p[o][k] = W2[o][k]*s[k];  b2p[o] = b2[o] + sum_k W2[o][k]*t[k]
// ---------------------------------------------------------------------------
__global__ void fold_kernel(const float* __restrict__ gamma,
                            const float* __restrict__ beta,
                            const float* __restrict__ W2,
                            const float* __restrict__ b2, float invM) {
    __shared__ float sc[F], tc[F];
    int t = threadIdx.x;  // 128 threads
    float S = g_stats[t], Q = g_stats[F + t];
    float mean = S * invM;
    float var = Q * invM - mean * mean;
    float s = gamma[t] * rsqrtf(var + 1e-5f);
    sc[t] = s;
    tc[t] = beta[t] - mean * s;
    __syncthreads();
    float acc = b2[t];
#pragma unroll
    for (int k = 0; k < F; k++) {
        float w = W2[t * F + k];
        g_W2p[t * F + k] = w * sc[k];
        acc += w * tc[k];
    }
    g_b2p[t] = acc;
}

// ---------------------------------------------------------------------------
extern "C" void kernel_launch(void* const* d_in, const int* in_sizes, int n_in,
                              void* d_out, int out_size) {
    const float* x         = (const float*)d_in[0];
    const void*  ei        = (const void*)d_in[1];
    const float* W1        = (const float*)d_in[2];
    const float* b1        = (const float*)d_in[3];
    const float* gamma     = (const float*)d_in[4];
    const float* beta      = (const float*)d_in[5];
    const float* W2        = (const float*)d_in[6];
    const float* b2        = (const float*)d_in[7];
    float* out             = (float*)d_out;

    int n_nodes = in_sizes[0] / F;
    int n_edges = in_sizes[1] / 2;

    cudaFuncSetAttribute(gemm_kernel<true>,
                         cudaFuncAttributeMaxDynamicSharedMemorySize, GEMM_SMEM);
    cudaFuncSetAttribute(gemm_kernel<false>,
                         cudaFuncAttributeMaxDynamicSharedMemorySize, GEMM_SMEM);

    detect_kernel<<<1, 32>>>((const int*)ei, in_sizes[1]);
    convert_kernel<<<(n_edges + 255) / 256, 256>>>(ei, n_edges, n_nodes);

    int n4 = n_nodes * (F / 4);
    init_kernel<<<(n4 + 255) / 256, 256>>>(x, n4);

    long long sthreads = (long long)n_edges * 32;
    scatter_kernel<<<(int)((sthreads + 255) / 256), 256>>>(x, n_edges);

    int gb = (n_nodes + 63) / 64;
    gemm_kernel<true><<<gb, 256, GEMM_SMEM>>>(W1, b1, nullptr, n_nodes);
    fold_kernel<<<1, F>>>(gamma, beta, W2, b2, 1.0f / (float)n_nodes);
    gemm_kernel<false><<<gb, 256, GEMM_SMEM>>>(nullptr, nullptr, out, n_nodes);
}